// round 2
// baseline (speedup 1.0000x reference)
#include <cuda_runtime.h>
#include <math.h>

#define NN 50000
#define NE 800000
#define NH 3          // heads
#define FMAX 192      // max H*Fo

// ---------------- scratch (device globals; no allocs allowed) ----------------
__device__ float    g_feat[NN * FMAX];   // per-layer projected features [N, H*Fo]
__device__ float    g_el[NN * NH];
__device__ float    g_er[NN * NH];
__device__ unsigned g_menc[NN * NH];     // encoded float max
__device__ float    g_s[NN * NH];        // softmax denominators
__device__ float    g_e[NE * NH];        // per-edge e, then ex
__device__ float    g_rst[NN * FMAX];    // aggregation output [N, H*Fo]
__device__ float    g_h[NN * 64];        // node features between layers

// order-preserving float<->uint encoding for atomicMax
__device__ __forceinline__ unsigned fenc(float f) {
    unsigned u = __float_as_uint(f);
    return (u & 0x80000000u) ? ~u : (u | 0x80000000u);
}
__device__ __forceinline__ float fdec(unsigned u) {
    return (u & 0x80000000u) ? __uint_as_float(u & 0x7fffffffu)
                             : __uint_as_float(~u);
}

// ---------------- kernels ----------------
__global__ void k_init(int nh, int nrst) {
    int i = blockIdx.x * blockDim.x + threadIdx.x;
    if (i < nh) { g_menc[i] = fenc(-INFINITY); g_s[i] = 0.f; }
    if (i < nrst) g_rst[i] = 0.f;
}

// out[n,c] = sum_k x[n,k] * W[k,c]   (c = h*Fo+f),  out -> g_feat
__global__ void k_gemm(const float* __restrict__ x, const float* __restrict__ W,
                       int fin, int ftot) {
    int i = blockIdx.x * blockDim.x + threadIdx.x;
    if (i >= NN * ftot) return;
    int n = i / ftot, c = i - n * ftot;
    const float* xr = x + n * fin;
    float acc = 0.f;
    #pragma unroll 4
    for (int k = 0; k < fin; k++) acc = fmaf(__ldg(xr + k), __ldg(W + k * ftot + c), acc);
    g_feat[i] = acc;
}

// el[n,h] = <feat[n,h,:], al[h,:]>, er likewise
__global__ void k_attn(const float* __restrict__ al, const float* __restrict__ ar, int fo) {
    int i = blockIdx.x * blockDim.x + threadIdx.x;
    if (i >= NN * NH) return;
    int n = i / NH, h = i - n * NH;
    const float* fr = g_feat + n * NH * fo + h * fo;
    float a = 0.f, b = 0.f;
    for (int f = 0; f < fo; f++) {
        float v = fr[f];
        a = fmaf(v, __ldg(al + h * fo + f), a);
        b = fmaf(v, __ldg(ar + h * fo + f), b);
    }
    g_el[i] = a;
    g_er[i] = b;
}

// pass 1: e = leaky_relu(el[src]+er[dst]); segment max into g_menc[dst]
__global__ void k_edge_max(const int* __restrict__ src, const int* __restrict__ dst) {
    int i = blockIdx.x * blockDim.x + threadIdx.x;
    if (i >= NE * NH) return;
    int e = i / NH, h = i - e * NH;
    int s = __ldg(src + e), d = __ldg(dst + e);
    float v = g_el[s * NH + h] + g_er[d * NH + h];
    v = v > 0.f ? v : 0.2f * v;
    g_e[i] = v;
    atomicMax(&g_menc[d * NH + h], fenc(v));
}

// pass 2: ex = exp(e - m[dst]); segment sum into g_s[dst]
__global__ void k_edge_exp(const int* __restrict__ dst) {
    int i = blockIdx.x * blockDim.x + threadIdx.x;
    if (i >= NE * NH) return;
    int e = i / NH, h = i - e * NH;
    int d = __ldg(dst + e);
    float ex = __expf(g_e[i] - fdec(g_menc[d * NH + h]));
    g_e[i] = ex;
    atomicAdd(&g_s[d * NH + h], ex);
}

// pass 3 (Fo=64): 16 threads per (edge,head), float4 vectorized scatter-add
__global__ void k_aggr64(const int* __restrict__ src, const int* __restrict__ dst) {
    int i = blockIdx.x * blockDim.x + threadIdx.x;
    if (i >= NE * NH * 16) return;
    int f4 = i & 15;
    int t  = i >> 4;
    int e = t / NH, h = t - e * NH;
    int s = __ldg(src + e), d = __ldg(dst + e);
    float alpha = g_e[e * NH + h] / g_s[d * NH + h];
    float4 v = *(const float4*)&g_feat[s * 192 + h * 64 + f4 * 4];
    float* r = &g_rst[d * 192 + h * 64 + f4 * 4];
    atomicAdd(r + 0, alpha * v.x);
    atomicAdd(r + 1, alpha * v.y);
    atomicAdd(r + 2, alpha * v.z);
    atomicAdd(r + 3, alpha * v.w);
}

// pass 3 (Fo=2): thread per (edge,head,f)
__global__ void k_aggr2(const int* __restrict__ src, const int* __restrict__ dst) {
    int i = blockIdx.x * blockDim.x + threadIdx.x;
    if (i >= NE * NH * 2) return;
    int f = i & 1;
    int t = i >> 1;
    int e = t / NH, h = t - e * NH;
    int s = __ldg(src + e), d = __ldg(dst + e);
    float alpha = g_e[e * NH + h] / g_s[d * NH + h];
    atomicAdd(&g_rst[d * 6 + h * 2 + f], alpha * g_feat[s * 6 + h * 2 + f]);
}

// out[n,f] = sum_h (rst[n,h,f] + bias[h,f])
__global__ void k_final(const float* __restrict__ bias, float* __restrict__ out, int fo) {
    int i = blockIdx.x * blockDim.x + threadIdx.x;
    if (i >= NN * fo) return;
    int n = i / fo, f = i - n * fo;
    float acc = 0.f;
    #pragma unroll
    for (int h = 0; h < NH; h++)
        acc += g_rst[n * NH * fo + h * fo + f] + __ldg(bias + h * fo + f);
    out[i] = acc;
}

// ---------------- host side ----------------
static inline int cdiv(int a, int b) { return (a + b - 1) / b; }

static void run_layer(const float* x, const int* src, const int* dst,
                      const float* W, const float* al, const float* ar, const float* bias,
                      int fin, int fo, float* out) {
    const int B = 256;
    int ftot = NH * fo;
    int nh = NN * NH, nrst = NN * ftot;
    k_init<<<cdiv(nrst > nh ? nrst : nh, B), B>>>(nh, nrst);
    k_gemm<<<cdiv(NN * ftot, B), B>>>(x, W, fin, ftot);
    k_attn<<<cdiv(NN * NH, B), B>>>(al, ar, fo);
    k_edge_max<<<cdiv(NE * NH, B), B>>>(src, dst);
    k_edge_exp<<<cdiv(NE * NH, B), B>>>(dst);
    if (fo == 64)
        k_aggr64<<<cdiv(NE * NH * 16, B), B>>>(src, dst);
    else
        k_aggr2<<<cdiv(NE * NH * 2, B), B>>>(src, dst);
    k_final<<<cdiv(NN * fo, B), B>>>(bias, out, fo);
}

extern "C" void kernel_launch(void* const* d_in, const int* in_sizes, int n_in,
                              void* d_out, int out_size) {
    const float* feats = (const float*)d_in[0];
    const int*   src   = (const int*)d_in[1];
    const int*   dst   = (const int*)d_in[2];
    const float* W1  = (const float*)d_in[3];
    const float* al1 = (const float*)d_in[4];
    const float* ar1 = (const float*)d_in[5];
    const float* b1  = (const float*)d_in[6];
    const float* W2  = (const float*)d_in[7];
    const float* al2 = (const float*)d_in[8];
    const float* ar2 = (const float*)d_in[9];
    const float* b2  = (const float*)d_in[10];
    const float* W3  = (const float*)d_in[11];
    const float* al3 = (const float*)d_in[12];
    const float* ar3 = (const float*)d_in[13];
    const float* b3  = (const float*)d_in[14];

    float* hbuf = nullptr;
    cudaGetSymbolAddress((void**)&hbuf, g_h);

    run_layer(feats, src, dst, W1, al1, ar1, b1, 9,  64, hbuf);
    run_layer(hbuf,  src, dst, W2, al2, ar2, b2, 64, 64, hbuf);
    run_layer(hbuf,  src, dst, W3, al3, ar3, b3, 64, 2,  (float*)d_out);
}

// round 3
// speedup vs baseline: 2.5643x; 2.5643x over previous
#include <cuda_runtime.h>
#include <math.h>

#define NN 50000
#define NE 800000
#define NH 3
#define FMAX 192

#define SCAN_B 512
#define SCAN_NB 98            // 98*512 = 50176 >= NN+1

// ---------------- scratch (device globals) ----------------
__device__ float g_feat[NN * FMAX];    // projected features [N, H*Fo]
__device__ float g_el[NN * NH];
__device__ float g_er[NN * NH];
__device__ float g_alpha[NE * NH];     // per-(csr_pos, head) e -> ex -> alpha
__device__ float g_rst[NN * FMAX];     // aggregation output
__device__ float g_h[NN * 64];         // inter-layer node features

__device__ int g_deg[SCAN_NB * SCAN_B];
__device__ int g_off[SCAN_NB * SCAN_B + 64];
__device__ int g_cur[NN];
__device__ int g_bsum[SCAN_NB + 8];
__device__ int g_csrc[NE];             // src node per CSR position

// ---------------- CSR build ----------------
__global__ void k_zero_deg() {
    int i = blockIdx.x * blockDim.x + threadIdx.x;
    if (i < SCAN_NB * SCAN_B) g_deg[i] = 0;
}

__global__ void k_count(const int* __restrict__ dst) {
    int e = blockIdx.x * blockDim.x + threadIdx.x;
    if (e < NE) atomicAdd(&g_deg[__ldg(dst + e)], 1);
}

__global__ void k_scan1() {
    __shared__ int s[SCAN_B];
    int t = threadIdx.x;
    int i = blockIdx.x * SCAN_B + t;
    int v = g_deg[i];
    s[t] = v;
    __syncthreads();
    for (int o = 1; o < SCAN_B; o <<= 1) {
        int x = (t >= o) ? s[t - o] : 0;
        __syncthreads();
        s[t] += x;
        __syncthreads();
    }
    g_off[i] = s[t] - v;               // exclusive within block
    if (t == SCAN_B - 1) g_bsum[blockIdx.x] = s[t];
}

__global__ void k_scan2() {
    if (threadIdx.x == 0) {
        int acc = 0;
        for (int b = 0; b < SCAN_NB; b++) {
            int v = g_bsum[b];
            g_bsum[b] = acc;
            acc += v;
        }
    }
}

__global__ void k_scan3() {
    int i = blockIdx.x * blockDim.x + threadIdx.x;
    if (i >= SCAN_NB * SCAN_B) return;
    int o = g_off[i] + g_bsum[i / SCAN_B];
    g_off[i] = o;
    if (i < NN) g_cur[i] = o;
}

__global__ void k_fill(const int* __restrict__ src, const int* __restrict__ dst) {
    int e = blockIdx.x * blockDim.x + threadIdx.x;
    if (e >= NE) return;
    int d = __ldg(dst + e);
    int pos = atomicAdd(&g_cur[d], 1);
    g_csrc[pos] = __ldg(src + e);
}

// ---------------- per-layer kernels ----------------
// scalar GEMM (used when ftot % 4 != 0)
__global__ void k_gemm(const float* __restrict__ x, const float* __restrict__ W,
                       int fin, int ftot) {
    int i = blockIdx.x * blockDim.x + threadIdx.x;
    if (i >= NN * ftot) return;
    int n = i / ftot, c = i - n * ftot;
    const float* xr = x + n * fin;
    float acc = 0.f;
    #pragma unroll 4
    for (int k = 0; k < fin; k++) acc = fmaf(__ldg(xr + k), __ldg(W + k * ftot + c), acc);
    g_feat[i] = acc;
}

// float4 GEMM over output channels
__global__ void k_gemm_v4(const float* __restrict__ x, const float* __restrict__ W,
                          int fin, int ftot) {
    int nvec = ftot >> 2;
    int i = blockIdx.x * blockDim.x + threadIdx.x;
    if (i >= NN * nvec) return;
    int n = i / nvec, c4 = i - n * nvec;
    const float* xr = x + n * fin;
    float4 acc = {0.f, 0.f, 0.f, 0.f};
    #pragma unroll 4
    for (int k = 0; k < fin; k++) {
        float xv = __ldg(xr + k);
        float4 w = __ldg((const float4*)(W + k * ftot + c4 * 4));
        acc.x = fmaf(xv, w.x, acc.x);
        acc.y = fmaf(xv, w.y, acc.y);
        acc.z = fmaf(xv, w.z, acc.z);
        acc.w = fmaf(xv, w.w, acc.w);
    }
    ((float4*)g_feat)[i] = acc;
}

__global__ void k_attn(const float* __restrict__ al, const float* __restrict__ ar, int fo) {
    int i = blockIdx.x * blockDim.x + threadIdx.x;
    if (i >= NN * NH) return;
    int n = i / NH, h = i - n * NH;
    const float* fr = g_feat + n * NH * fo + h * fo;
    float a = 0.f, b = 0.f;
    for (int f = 0; f < fo; f++) {
        float v = fr[f];
        a = fmaf(v, __ldg(al + h * fo + f), a);
        b = fmaf(v, __ldg(ar + h * fo + f), b);
    }
    g_el[i] = a;
    g_er[i] = b;
}

// thread per (dst, head): compute edge softmax alphas over CSR segment
__global__ void k_alpha() {
    int i = blockIdx.x * blockDim.x + threadIdx.x;
    if (i >= NN * NH) return;
    int d = i / NH, h = i - d * NH;
    int b0 = g_off[d], b1 = g_off[d + 1];
    if (b0 == b1) return;
    float erd = g_er[d * NH + h];
    float m = -INFINITY;
    for (int p = b0; p < b1; p++) {
        int s = g_csrc[p];
        float v = g_el[s * NH + h] + erd;
        v = v > 0.f ? v : 0.2f * v;
        g_alpha[p * NH + h] = v;
        m = fmaxf(m, v);
    }
    float sum = 0.f;
    for (int p = b0; p < b1; p++) {
        float ex = __expf(g_alpha[p * NH + h] - m);
        g_alpha[p * NH + h] = ex;
        sum += ex;
    }
    float inv = 1.f / sum;
    for (int p = b0; p < b1; p++) g_alpha[p * NH + h] *= inv;
}

// warp per (dst, head), lane = float2 of features (Fo=64)
__global__ void k_aggr64_csr() {
    int gw = (blockIdx.x * blockDim.x + threadIdx.x) >> 5;
    if (gw >= NN * NH) return;
    int lane = threadIdx.x & 31;
    int d = gw / NH, h = gw - d * NH;
    int b0 = g_off[d], b1 = g_off[d + 1];
    float2 acc = {0.f, 0.f};
    const float2* featp = (const float2*)g_feat;
    int fvec = h * 32 + lane;          // float2 index within a node's 192 floats
    for (int p = b0; p < b1; p++) {
        int s = g_csrc[p];
        float a = g_alpha[p * NH + h];
        float2 v = featp[s * 96 + fvec];
        acc.x = fmaf(a, v.x, acc.x);
        acc.y = fmaf(a, v.y, acc.y);
    }
    ((float2*)g_rst)[d * 96 + fvec] = acc;
}

// thread per (dst, head) for Fo=2
__global__ void k_aggr2_csr() {
    int i = blockIdx.x * blockDim.x + threadIdx.x;
    if (i >= NN * NH) return;
    int d = i / NH, h = i - d * NH;
    int b0 = g_off[d], b1 = g_off[d + 1];
    float a0 = 0.f, a1 = 0.f;
    for (int p = b0; p < b1; p++) {
        int s = g_csrc[p];
        float a = g_alpha[p * NH + h];
        a0 = fmaf(a, g_feat[s * 6 + h * 2 + 0], a0);
        a1 = fmaf(a, g_feat[s * 6 + h * 2 + 1], a1);
    }
    g_rst[d * 6 + h * 2 + 0] = a0;
    g_rst[d * 6 + h * 2 + 1] = a1;
}

// out[n,f] = sum_h (rst[n,h,f] + bias[h,f])
__global__ void k_final(const float* __restrict__ bias, float* __restrict__ out, int fo) {
    int i = blockIdx.x * blockDim.x + threadIdx.x;
    if (i >= NN * fo) return;
    int n = i / fo, f = i - n * fo;
    float acc = 0.f;
    #pragma unroll
    for (int h = 0; h < NH; h++)
        acc += g_rst[n * NH * fo + h * fo + f] + __ldg(bias + h * fo + f);
    out[i] = acc;
}

// ---------------- host side ----------------
static inline int cdiv(int a, int b) { return (a + b - 1) / b; }

static void run_layer(const float* x, const float* W, const float* al,
                      const float* ar, const float* bias,
                      int fin, int fo, float* out) {
    const int B = 256;
    int ftot = NH * fo;
    if ((ftot & 3) == 0)
        k_gemm_v4<<<cdiv(NN * (ftot >> 2), B), B>>>(x, W, fin, ftot);
    else
        k_gemm<<<cdiv(NN * ftot, B), B>>>(x, W, fin, ftot);
    k_attn<<<cdiv(NN * NH, B), B>>>(al, ar, fo);
    k_alpha<<<cdiv(NN * NH, B), B>>>();
    if (fo == 64)
        k_aggr64_csr<<<cdiv(NN * NH * 32, B), B>>>();
    else
        k_aggr2_csr<<<cdiv(NN * NH, B), B>>>();
    k_final<<<cdiv(NN * fo, B), B>>>(bias, out, fo);
}

extern "C" void kernel_launch(void* const* d_in, const int* in_sizes, int n_in,
                              void* d_out, int out_size) {
    const float* feats = (const float*)d_in[0];
    const int*   src   = (const int*)d_in[1];
    const int*   dst   = (const int*)d_in[2];
    const float* W1  = (const float*)d_in[3];
    const float* al1 = (const float*)d_in[4];
    const float* ar1 = (const float*)d_in[5];
    const float* b1  = (const float*)d_in[6];
    const float* W2  = (const float*)d_in[7];
    const float* al2 = (const float*)d_in[8];
    const float* ar2 = (const float*)d_in[9];
    const float* b2  = (const float*)d_in[10];
    const float* W3  = (const float*)d_in[11];
    const float* al3 = (const float*)d_in[12];
    const float* ar3 = (const float*)d_in[13];
    const float* b3  = (const float*)d_in[14];

    const int B = 256;

    // Build CSR once (reused by all 3 layers)
    k_zero_deg<<<cdiv(SCAN_NB * SCAN_B, B), B>>>();
    k_count<<<cdiv(NE, B), B>>>(dst);
    k_scan1<<<SCAN_NB, SCAN_B>>>();
    k_scan2<<<1, 32>>>();
    k_scan3<<<cdiv(SCAN_NB * SCAN_B, B), B>>>();
    k_fill<<<cdiv(NE, B), B>>>(src, dst);

    float* hbuf = nullptr;
    cudaGetSymbolAddress((void**)&hbuf, g_h);

    run_layer(feats, W1, al1, ar1, b1, 9,  64, hbuf);
    run_layer(hbuf,  W2, al2, ar2, b2, 64, 64, hbuf);
    run_layer(hbuf,  W3, al3, ar3, b3, 64, 2,  (float*)d_out);
}